// round 1
// baseline (speedup 1.0000x reference)
#include <cuda_runtime.h>

// ---------------------------------------------------------------------------
// OutputHead: e3nn o3.Linear 1e block (64 -> 1 base + 14 relative) + ragged
// un-padding gather, fused into a single pass over the feature matrix.
//
// Inputs (metadata order):
//   d_in[0]: features  float32 [R, 320]   (vec block = cols 128..319)
//   d_in[1]: w_base    float32 [64, 1]
//   d_in[2]: w_rel     float32 [64, 14]
//   d_in[3]: residue_index_atomwise  int64-or-int32 [N]  (sorted, nondecreasing)
// Output:
//   d_out:  float32 [R*3 + N*3]  = concat(base_coords, unpadded_relative)
// ---------------------------------------------------------------------------

#define RMAX 200000
#define MUL_IN 64
#define PAD 14
#define NORM 0.125f   // 1/sqrt(64)

__device__ int g_offsets[RMAX];   // first atom index of each residue
__device__ int g_is64;            // 1 if index buffer is int64, 0 if int32

// --- detect element width of the residue index buffer -----------------------
// If data is little-endian int64 with values < 2^31, the odd 32-bit words of
// the first elements are all zero. For this dataset idx[1] = 1 under int32,
// so the test is unambiguous.
__global__ void detect_idx_width_kernel(const int* __restrict__ words, long long n_elems)
{
    if (blockIdx.x != 0 || threadIdx.x != 0) return;
    int is64 = 1;
    int m = (int)(n_elems < 32 ? n_elems : 32);
    for (int i = 0; i < m; i++) {
        if (words[2 * i + 1] != 0) { is64 = 0; break; }
    }
    g_is64 = is64;
}

// --- offsets: mark the first atom of each residue ---------------------------
__global__ void offsets_kernel(const void* __restrict__ idx, long long N)
{
    long long j = (long long)blockIdx.x * blockDim.x + threadIdx.x;
    if (j >= N) return;
    long long r, rprev;
    if (g_is64) {
        const long long* p = (const long long*)idx;
        r = p[j];
        rprev = (j > 0) ? p[j - 1] : -1;
    } else {
        const int* p = (const int*)idx;
        r = p[j];
        rprev = (j > 0) ? (long long)p[j - 1] : -1;
    }
    if (r != rprev) g_offsets[r] = (int)j;
}

// --- main fused kernel: one thread per residue -------------------------------
__global__ void __launch_bounds__(256)
residue_kernel(const float* __restrict__ feat,
               const float* __restrict__ wb,
               const float* __restrict__ wr,
               float* __restrict__ out,
               int R, long long N)
{
    __shared__ float s_wb[MUL_IN];
    __shared__ float s_wr[MUL_IN * PAD];
    for (int i = threadIdx.x; i < MUL_IN; i += blockDim.x)
        s_wb[i] = wb[i] * NORM;
    for (int i = threadIdx.x; i < MUL_IN * PAD; i += blockDim.x)
        s_wr[i] = wr[i] * NORM;
    __syncthreads();

    int r = blockIdx.x * blockDim.x + threadIdx.x;
    if (r >= R) return;

    // acc[0..41] = rel[p][xyz], acc[42..44] = base[xyz]
    float acc[45];
#pragma unroll
    for (int i = 0; i < 45; i++) acc[i] = 0.0f;

    // vec block: 192 floats starting at byte offset 512 of a 1280-byte row.
    // 16B-aligned -> 48 float4 loads, 3 float4 per 4 channels.
    const float4* vp = reinterpret_cast<const float4*>(feat + (size_t)r * 320 + 128);

#pragma unroll 2
    for (int g = 0; g < 16; g++) {
        float4 A = __ldg(vp + g * 3 + 0);
        float4 B = __ldg(vp + g * 3 + 1);
        float4 C = __ldg(vp + g * 3 + 2);
        float vx[4] = { A.x, A.w, B.z, C.y };
        float vy[4] = { A.y, B.x, B.w, C.z };
        float vz[4] = { A.z, B.y, C.x, C.w };
#pragma unroll
        for (int k = 0; k < 4; k++) {
            const int c = g * 4 + k;
            float wbv = s_wb[c];
            acc[42] = fmaf(vx[k], wbv, acc[42]);
            acc[43] = fmaf(vy[k], wbv, acc[43]);
            acc[44] = fmaf(vz[k], wbv, acc[44]);
#pragma unroll
            for (int p = 0; p < PAD; p++) {
                float w = s_wr[c * PAD + p];
                acc[p * 3 + 0] = fmaf(vx[k], w, acc[p * 3 + 0]);
                acc[p * 3 + 1] = fmaf(vy[k], w, acc[p * 3 + 1]);
                acc[p * 3 + 2] = fmaf(vz[k], w, acc[p * 3 + 2]);
            }
        }
    }

    // base_coords
    float* ob = out + (size_t)r * 3;
    ob[0] = acc[42];
    ob[1] = acc[43];
    ob[2] = acc[44];

    // un-padded relative coords written directly (offsets partition [0, N))
    int off = g_offsets[r];
    int cnt = ((r + 1 < R) ? g_offsets[r + 1] : (int)N) - off;
    float* od = out + (size_t)R * 3 + (size_t)off * 3;
#pragma unroll
    for (int p = 0; p < PAD; p++) {
        if (p < cnt) {
            od[p * 3 + 0] = acc[p * 3 + 0];
            od[p * 3 + 1] = acc[p * 3 + 1];
            od[p * 3 + 2] = acc[p * 3 + 2];
        }
    }
}

extern "C" void kernel_launch(void* const* d_in, const int* in_sizes, int n_in,
                              void* d_out, int out_size)
{
    const float* feat = (const float*)d_in[0];
    const float* wb   = (const float*)d_in[1];
    const float* wr   = (const float*)d_in[2];
    const void*  idx  = d_in[3];
    float* out = (float*)d_out;

    int R = in_sizes[0] / 320;
    long long N = (long long)in_sizes[3];

    detect_idx_width_kernel<<<1, 32>>>((const int*)idx, N);

    int tb = 256;
    int nblk_off = (int)((N + tb - 1) / tb);
    offsets_kernel<<<nblk_off, tb>>>(idx, N);

    int nblk_res = (R + tb - 1) / tb;
    residue_kernel<<<nblk_res, tb>>>(feat, wb, wr, out, R, N);
}